// round 8
// baseline (speedup 1.0000x reference)
#include <cuda_runtime.h>
#include <cstdint>

#define NN 50000
#define EE 800000
#define CC 128
#define SCAN_BLOCKS 196   // ceil(50000/256)

// Scratch (static __device__ arrays — allocation-free)
__device__ float g_hs[(size_t)NN * CC];   // hs[j] = (x@W)[j]  (UNscaled)
__device__ float g_dinv[NN];
__device__ int   g_deg[NN];               // edge-only in-degree (self excluded)
__device__ int   g_rowptr[NN + 1];
__device__ int   g_tmp[NN];               // per-block exclusive scan
__device__ int   g_bsum[256];             // per-block sums
__device__ int   g_fill[NN];              // fill cursors
__device__ int   g_srcidx[EE];            // CSR column (src) indices

// ---------------------------------------------------------------------------
__global__ void deg_init_kernel() {
    int i = blockIdx.x * blockDim.x + threadIdx.x;
    if (i < NN) g_deg[i] = 0;
}

__global__ void deg_count_kernel(const int* __restrict__ ei) {
    int e = blockIdx.x * blockDim.x + threadIdx.x;
    if (e < EE) atomicAdd(&g_deg[ei[EE + e]], 1);
}

// per-block exclusive scan of deg
__global__ void scan1_kernel() {
    __shared__ int s[256];
    int t = threadIdx.x;
    int i = blockIdx.x * 256 + t;
    int val = (i < NN) ? g_deg[i] : 0;
    s[t] = val;
    __syncthreads();
#pragma unroll
    for (int off = 1; off < 256; off <<= 1) {
        int v = (t >= off) ? s[t - off] : 0;
        __syncthreads();
        s[t] += v;
        __syncthreads();
    }
    if (i < NN) g_tmp[i] = s[t] - val;       // exclusive
    if (t == 255) g_bsum[blockIdx.x] = s[255];
}

// scan2+scan3 fused: each block warp-reduces its base from preceding block
// sums, then finalizes rowptr / fill / dinv.
__global__ void scan23_kernel() {
    __shared__ int sbase;
    int t = threadIdx.x;
    if (t < 32) {
        int sum = 0;
        for (int j = t; j < blockIdx.x; j += 32) sum += g_bsum[j];
#pragma unroll
        for (int off = 16; off > 0; off >>= 1)
            sum += __shfl_xor_sync(0xffffffffu, sum, off);
        if (t == 0) sbase = sum;
    }
    __syncthreads();
    int i = blockIdx.x * 256 + t;
    if (i < NN) {
        g_rowptr[i] = g_tmp[i] + sbase;
        g_fill[i] = 0;
        g_dinv[i] = rsqrtf((float)(g_deg[i] + 1));
    }
    if (i == 0) g_rowptr[NN] = EE;
}

// bucket edges into CSR (order within bucket irrelevant)
__global__ void fill_kernel(const int* __restrict__ ei) {
    int e = blockIdx.x * blockDim.x + threadIdx.x;
    if (e < EE) {
        int src = ei[e];
        int dst = ei[EE + e];
        int pos = atomicAdd(&g_fill[dst], 1);
        g_srcidx[g_rowptr[dst] + pos] = src;
    }
}

// ---------------------------------------------------------------------------
// GEMM (fp32 SIMT, proven): hs = x @ W, unscaled.
// 256 threads, 64 rows/block. Thread = 8 rows (warp-group) x 4 cols (lane).
__global__ void gemm_kernel(const float* __restrict__ x,
                            const float* __restrict__ w) {
    __shared__ float4 sx[64][32];   // 32 KB
    const int row0 = blockIdx.x * 64;
    const int t = threadIdx.x;
    const int lane = t & 31;
    const int wg = t >> 5;          // 8 warps
    const int r0 = wg * 8;

    const float4* x4 = (const float4*)x;
    for (int i = t; i < 64 * 32; i += 256) {
        int r = i >> 5, c = i & 31;
        int row = row0 + r;
        sx[r][c] = (row < NN) ? x4[(size_t)row * 32 + c]
                              : make_float4(0.f, 0.f, 0.f, 0.f);
    }
    __syncthreads();

    float acc[8][4] = {};
    const float4* w4 = (const float4*)w;

#pragma unroll 2
    for (int k4 = 0; k4 < 32; k4++) {
        float4 wv0 = w4[(k4 * 4 + 0) * 32 + lane];
        float4 wv1 = w4[(k4 * 4 + 1) * 32 + lane];
        float4 wv2 = w4[(k4 * 4 + 2) * 32 + lane];
        float4 wv3 = w4[(k4 * 4 + 3) * 32 + lane];
#pragma unroll
        for (int r = 0; r < 8; r++) {
            float4 xv = sx[r0 + r][k4];  // broadcast, conflict-free
            acc[r][0] += xv.x * wv0.x; acc[r][1] += xv.x * wv0.y;
            acc[r][2] += xv.x * wv0.z; acc[r][3] += xv.x * wv0.w;
            acc[r][0] += xv.y * wv1.x; acc[r][1] += xv.y * wv1.y;
            acc[r][2] += xv.y * wv1.z; acc[r][3] += xv.y * wv1.w;
            acc[r][0] += xv.z * wv2.x; acc[r][1] += xv.z * wv2.y;
            acc[r][2] += xv.z * wv2.z; acc[r][3] += xv.z * wv2.w;
            acc[r][0] += xv.w * wv3.x; acc[r][1] += xv.w * wv3.y;
            acc[r][2] += xv.w * wv3.z; acc[r][3] += xv.w * wv3.w;
        }
    }

    float4* hs4 = (float4*)g_hs;
#pragma unroll
    for (int r = 0; r < 8; r++) {
        int row = row0 + r0 + r;
        if (row < NN)
            hs4[(size_t)row * 32 + lane] =
                make_float4(acc[r][0], acc[r][1], acc[r][2], acc[r][3]);
    }
}

// ---------------------------------------------------------------------------
// CSR gather: one warp per node. norm applied here:
//   acc = hs[i]*dinv[i] + sum_j hs[j]*dinv[j];  out = relu(acc*dinv[i] + b)
__global__ void gather_kernel(float* __restrict__ out,
                              const float* __restrict__ bias) {
    int warp = (blockIdx.x * blockDim.x + threadIdx.x) >> 5;
    if (warp >= NN) return;
    int lane = threadIdx.x & 31;
    const float4* hs4 = (const float4*)g_hs;

    int start = g_rowptr[warp];
    int end   = g_rowptr[warp + 1];
    float di = g_dinv[warp];

    float4 self = __ldg(&hs4[(size_t)warp * 32 + lane]);
    float4 acc = make_float4(self.x * di, self.y * di, self.z * di, self.w * di);

    for (int c = start; c < end; c += 32) {
        int n = min(32, end - c);
        int myidx = (c + lane < end) ? __ldg(&g_srcidx[c + lane]) : 0;
#pragma unroll 4
        for (int j = 0; j < n; j++) {
            int s = __shfl_sync(0xffffffffu, myidx, j);
            float ds = __ldg(&g_dinv[s]);                       // broadcast
            float4 v = __ldg(&hs4[(size_t)s * 32 + lane]);
            acc.x = fmaf(v.x, ds, acc.x);
            acc.y = fmaf(v.y, ds, acc.y);
            acc.z = fmaf(v.z, ds, acc.z);
            acc.w = fmaf(v.w, ds, acc.w);
        }
    }

    float4 b = ((const float4*)bias)[lane];
    float4 o;
    o.x = fmaxf(fmaf(acc.x, di, b.x), 0.f);
    o.y = fmaxf(fmaf(acc.y, di, b.y), 0.f);
    o.z = fmaxf(fmaf(acc.z, di, b.z), 0.f);
    o.w = fmaxf(fmaf(acc.w, di, b.w), 0.f);
    ((float4*)out)[(size_t)warp * 32 + lane] = o;
}

// ---------------------------------------------------------------------------
extern "C" void kernel_launch(void* const* d_in, const int* in_sizes, int n_in,
                              void* d_out, int out_size) {
    const float* x    = (const float*)d_in[0];   // [50000,128] f32
    const int*   ei   = (const int*)d_in[1];     // [2,800000] int32
    const float* w    = (const float*)d_in[2];   // [128,128] f32
    const float* bias = (const float*)d_in[3];   // [128] f32
    float* out = (float*)d_out;                  // [50000,128] f32
    (void)in_sizes; (void)n_in; (void)out_size;

    // Fork the capture: CSR build (side stream) runs concurrently with the
    // GEMM (main stream). Kernel launches + event edges only — capturable.
    cudaStream_t s2;
    cudaStreamCreateWithFlags(&s2, cudaStreamNonBlocking);
    cudaEvent_t eFork, eJoin;
    cudaEventCreateWithFlags(&eFork, cudaEventDisableTiming);
    cudaEventCreateWithFlags(&eJoin, cudaEventDisableTiming);

    cudaEventRecord(eFork, 0);
    cudaStreamWaitEvent(s2, eFork, 0);

    // Branch B (side stream): CSR build + dinv
    deg_init_kernel<<<(NN + 255) / 256, 256, 0, s2>>>();
    deg_count_kernel<<<(EE + 255) / 256, 256, 0, s2>>>(ei);
    scan1_kernel<<<SCAN_BLOCKS, 256, 0, s2>>>();
    scan23_kernel<<<SCAN_BLOCKS, 256, 0, s2>>>();
    fill_kernel<<<(EE + 255) / 256, 256, 0, s2>>>(ei);

    // Branch A (main stream): hs = x @ W (no CSR/dinv dependency)
    gemm_kernel<<<(NN + 63) / 64, 256>>>(x, w);

    // Join: gather needs both branches
    cudaEventRecord(eJoin, s2);
    cudaStreamWaitEvent(0, eJoin, 0);

    gather_kernel<<<(NN * 32 + 255) / 256, 256>>>(out, bias);

    cudaEventDestroy(eFork);
    cudaEventDestroy(eJoin);
    cudaStreamDestroy(s2);
}